// round 7
// baseline (speedup 1.0000x reference)
#include <cuda_runtime.h>
#include <cuda_bf16.h>
#include <math.h>
#include <stdint.h>

// ---------------------------------------------------------------------------
// Swin Transformer block, B=16, H=W=56, C=256, NH=8, WS=7, SS=3, HD=32, N=49
// R6: fuse LN1->QKV, LN2->fc1 (weight folding + in-register normalize),
//     fuse unshift+residual into proj epilogue, hid in bf16.
// ---------------------------------------------------------------------------

#define Bv    16
#define Hv    56
#define Wv    56
#define Cv    256
#define NHv   8
#define WSv   7
#define SSv   3
#define HDv   32
#define Nv    49
#define NWIN  64
#define BW    1024
#define TOK   50176
#define SCALEv 0.17677669529663687f

// scratch
__device__ float g_qkv[TOK * 3 * Cv];
__device__ float g_atto[TOK * Cv];
__device__ float g_x1[TOK * Cv];
__device__ __nv_bfloat16 g_hid[TOK * 4 * Cv];
__device__ float g_mu1[TOK], g_rs1[TOK];
__device__ float g_mu2[TOK], g_rs2[TOK];
__device__ float g_qkvwf[3 * Cv * Cv], g_qkvbf[3 * Cv];
__device__ float g_fc1wf[4 * Cv * Cv], g_fc1bf[4 * Cv];

// window-order token t -> source token in x (forward shift + partition)
__device__ __forceinline__ int win_src(int t) {
    int win = t / Nv, n = t % Nv;
    int b = win >> 6, w = win & 63;
    int i = (w >> 3) * WSv + n / WSv;
    int j = (w & 7) * WSv + n % WSv;
    int si = (i + SSv) % Hv;
    int sj = (j + SSv) % Wv;
    return b * (Hv * Wv) + si * Wv + sj;
}
// window-order row -> output token (window reverse + unshift)
__device__ __forceinline__ int inv_tok(int row) {
    int win = row / Nv, n = row % Nv;
    int b = win >> 6, w = win & 63;
    int p = (w >> 3) * WSv + n / WSv;
    int q = (w & 7) * WSv + n % WSv;
    int i = (p + SSv) % Hv;
    int j = (q + SSv) % Wv;
    return b * (Hv * Wv) + i * Wv + j;
}

// ---------------------------------------------------------------------------
// fold: Wg[n][k] = W[n][k]*g[k];  bg[n] = bias[n] + sum_k W[n][k]*beta[k]
// one block (256 thr) per output row n; K == 256.
// ---------------------------------------------------------------------------
__global__ __launch_bounds__(256) void fold_kernel(
    const float* __restrict__ W, const float* __restrict__ bias,
    const float* __restrict__ g, const float* __restrict__ be,
    float* __restrict__ Wg, float* __restrict__ bg)
{
    int n = blockIdx.x, k = threadIdx.x;
    float w = W[n * Cv + k];
    Wg[n * Cv + k] = w * g[k];
    float p = w * be[k];
    #pragma unroll
    for (int o = 16; o > 0; o >>= 1) p += __shfl_xor_sync(0xffffffffu, p, o);
    __shared__ float ws[8];
    if ((k & 31) == 0) ws[k >> 5] = p;
    __syncthreads();
    if (k == 0) {
        float s = 0.f;
        #pragma unroll
        for (int i = 0; i < 8; i++) s += ws[i];
        bg[n] = bias[n] + s;
    }
}

// ---------------------------------------------------------------------------
// per-token LN stats. warp per token, 8 tokens/block.
// mode 1: token index is window-order (gather via win_src); mode 0: identity.
// ---------------------------------------------------------------------------
__global__ __launch_bounds__(256) void ln_stats_kernel(
    const float* __restrict__ x, float* __restrict__ MU, float* __restrict__ RS,
    int mode)
{
    int warp = threadIdx.x >> 5, lane = threadIdx.x & 31;
    int t = blockIdx.x * 8 + warp;
    int src = mode ? win_src(t) : t;
    const float4* xr = (const float4*)(x + (size_t)src * Cv);
    float4 v0 = xr[lane], v1 = xr[lane + 32];
    float s  = v0.x + v0.y + v0.z + v0.w + v1.x + v1.y + v1.z + v1.w;
    float s2 = v0.x*v0.x + v0.y*v0.y + v0.z*v0.z + v0.w*v0.w
             + v1.x*v1.x + v1.y*v1.y + v1.z*v1.z + v1.w*v1.w;
    #pragma unroll
    for (int o = 16; o > 0; o >>= 1) {
        s  += __shfl_xor_sync(0xffffffffu, s,  o);
        s2 += __shfl_xor_sync(0xffffffffu, s2, o);
    }
    if (lane == 0) {
        float mu  = s * (1.f / Cv);
        float var = s2 * (1.f / Cv) - mu * mu;
        MU[t] = mu;
        RS[t] = rsqrtf(var + 1e-5f);
    }
}

// ---------------------------------------------------------------------------
// TF32 tensor-core GEMM, templated.
// AM (A-side): 0 plain fp32; 1 LN-normalize + window gather; 2 LN-normalize
//              identity order; 3 bf16 input.
// OM (output): 0 plain (+bias, +res at same index); 1 GELU + bf16 store;
//              2 unshift row-remap + res (residual indexed at remapped row).
// ---------------------------------------------------------------------------
#define PAD 4
__device__ __forceinline__ uint32_t f2tf32(float f) {
    uint32_t r;
    asm("cvt.rna.tf32.f32 %0, %1;" : "=r"(r) : "f"(f));
    return r;
}
__device__ __forceinline__ void mma_tf32(float* c, const uint32_t* a, const uint32_t* b) {
    asm volatile(
        "mma.sync.aligned.m16n8k8.row.col.f32.tf32.tf32.f32 "
        "{%0,%1,%2,%3}, {%4,%5,%6,%7}, {%8,%9}, {%0,%1,%2,%3};"
        : "+f"(c[0]), "+f"(c[1]), "+f"(c[2]), "+f"(c[3])
        : "r"(a[0]), "r"(a[1]), "r"(a[2]), "r"(a[3]), "r"(b[0]), "r"(b[1]));
}

template<int AM>
__device__ __forceinline__ float4 ldA(const void* rp, int k, float mu, float rs) {
    if (AM == 3) {
        const __nv_bfloat162* p = (const __nv_bfloat162*)((const __nv_bfloat16*)rp + k);
        float2 f0 = __bfloat1622float2(p[0]);
        float2 f1 = __bfloat1622float2(p[1]);
        return make_float4(f0.x, f0.y, f1.x, f1.y);
    } else {
        float4 v = *(const float4*)((const float*)rp + k);
        if (AM == 1 || AM == 2) {
            v.x = (v.x - mu) * rs; v.y = (v.y - mu) * rs;
            v.z = (v.z - mu) * rs; v.w = (v.w - mu) * rs;
        }
        return v;
    }
}

template<int AM, int OM>
__global__ __launch_bounds__(256) void tf32_gemm_kernel(
    const void* __restrict__ A, const float* __restrict__ Wt,
    const float* __restrict__ bias, const float* __restrict__ res,
    void* __restrict__ Cout, const float* __restrict__ MU,
    const float* __restrict__ RS, int M, int Nc, int K)
{
    __shared__ uint32_t As[16][128 + PAD];
    __shared__ uint32_t Bs[16][128 + PAD];

    int tid  = threadIdx.x;
    int warp = tid >> 5, lane = tid & 31;
    int wm   = (warp >> 2) * 64;
    int wn   = (warp & 3) * 32;
    int bm   = blockIdx.y * 128, bn = blockIdx.x * 128;

    float acc[4][4][4];
    #pragma unroll
    for (int mt = 0; mt < 4; mt++)
        #pragma unroll
        for (int nt = 0; nt < 4; nt++)
            #pragma unroll
            for (int i = 0; i < 4; i++) acc[mt][nt][i] = 0.f;

    int ar0 = tid >> 2,        ac0 = (tid & 3) * 4;
    int ar1 = (tid >> 2) + 64, ac1 = ac0;

    // per-thread A row pointers + LN stats
    int t0 = bm + ar0, t1 = bm + ar1;
    const void *rp0, *rp1;
    float mu0 = 0.f, rs0 = 0.f, mu1 = 0.f, rs1 = 0.f;
    if (AM == 1) {
        rp0 = (const float*)A + (size_t)win_src(t0) * K;
        rp1 = (const float*)A + (size_t)win_src(t1) * K;
        mu0 = MU[t0]; rs0 = RS[t0]; mu1 = MU[t1]; rs1 = RS[t1];
    } else if (AM == 2) {
        rp0 = (const float*)A + (size_t)t0 * K;
        rp1 = (const float*)A + (size_t)t1 * K;
        mu0 = MU[t0]; rs0 = RS[t0]; mu1 = MU[t1]; rs1 = RS[t1];
    } else if (AM == 3) {
        rp0 = (const __nv_bfloat16*)A + (size_t)t0 * K;
        rp1 = (const __nv_bfloat16*)A + (size_t)t1 * K;
    } else {
        rp0 = (const float*)A + (size_t)t0 * K;
        rp1 = (const float*)A + (size_t)t1 * K;
    }
    const float* Brow0 = Wt + (size_t)(bn + ar0) * K;
    const float* Brow1 = Wt + (size_t)(bn + ar1) * K;

    float4 a_reg[2], b_reg[2];
    a_reg[0] = ldA<AM>(rp0, ac0, mu0, rs0);
    a_reg[1] = ldA<AM>(rp1, ac1, mu1, rs1);
    b_reg[0] = *(const float4*)(Brow0 + ac0);
    b_reg[1] = *(const float4*)(Brow1 + ac1);

    for (int k0 = 0; k0 < K; k0 += 16) {
        __syncthreads();
        As[ac0 + 0][ar0] = f2tf32(a_reg[0].x);
        As[ac0 + 1][ar0] = f2tf32(a_reg[0].y);
        As[ac0 + 2][ar0] = f2tf32(a_reg[0].z);
        As[ac0 + 3][ar0] = f2tf32(a_reg[0].w);
        As[ac1 + 0][ar1] = f2tf32(a_reg[1].x);
        As[ac1 + 1][ar1] = f2tf32(a_reg[1].y);
        As[ac1 + 2][ar1] = f2tf32(a_reg[1].z);
        As[ac1 + 3][ar1] = f2tf32(a_reg[1].w);
        Bs[ac0 + 0][ar0] = f2tf32(b_reg[0].x);
        Bs[ac0 + 1][ar0] = f2tf32(b_reg[0].y);
        Bs[ac0 + 2][ar0] = f2tf32(b_reg[0].z);
        Bs[ac0 + 3][ar0] = f2tf32(b_reg[0].w);
        Bs[ac1 + 0][ar1] = f2tf32(b_reg[1].x);
        Bs[ac1 + 1][ar1] = f2tf32(b_reg[1].y);
        Bs[ac1 + 2][ar1] = f2tf32(b_reg[1].z);
        Bs[ac1 + 3][ar1] = f2tf32(b_reg[1].w);
        __syncthreads();

        if (k0 + 16 < K) {
            int kn = k0 + 16;
            a_reg[0] = ldA<AM>(rp0, kn + ac0, mu0, rs0);
            a_reg[1] = ldA<AM>(rp1, kn + ac1, mu1, rs1);
            b_reg[0] = *(const float4*)(Brow0 + kn + ac0);
            b_reg[1] = *(const float4*)(Brow1 + kn + ac1);
        }

        #pragma unroll
        for (int ks = 0; ks < 2; ks++) {
            int kb = ks * 8;
            int qr = lane >> 2, qc = lane & 3;
            uint32_t af[4][4], bf[4][2];
            #pragma unroll
            for (int mt = 0; mt < 4; mt++) {
                int m = wm + mt * 16 + qr;
                af[mt][0] = As[kb + qc][m];
                af[mt][1] = As[kb + qc][m + 8];
                af[mt][2] = As[kb + qc + 4][m];
                af[mt][3] = As[kb + qc + 4][m + 8];
            }
            #pragma unroll
            for (int nt = 0; nt < 4; nt++) {
                int n = wn + nt * 8 + qr;
                bf[nt][0] = Bs[kb + qc][n];
                bf[nt][1] = Bs[kb + qc + 4][n];
            }
            #pragma unroll
            for (int mt = 0; mt < 4; mt++)
                #pragma unroll
                for (int nt = 0; nt < 4; nt++)
                    mma_tf32(acc[mt][nt], af[mt], bf[nt]);
        }
    }

    const float INV_SQRT2 = 0.70710678118654752f;
    int qr = lane >> 2, qc = lane & 3;
    #pragma unroll
    for (int mt = 0; mt < 4; mt++) {
        #pragma unroll
        for (int half = 0; half < 2; half++) {
            int row = bm + wm + mt * 16 + qr + half * 8;
            int orow = (OM == 2) ? inv_tok(row) : row;
            #pragma unroll
            for (int nt = 0; nt < 4; nt++) {
                int col = bn + wn + nt * 8 + qc * 2;
                float v0 = acc[mt][nt][half * 2 + 0];
                float v1 = acc[mt][nt][half * 2 + 1];
                if (bias) { v0 += bias[col]; v1 += bias[col + 1]; }
                size_t oidx = (size_t)orow * Nc + col;
                if (OM == 1) {
                    v0 = 0.5f * v0 * (1.f + erff(v0 * INV_SQRT2));
                    v1 = 0.5f * v1 * (1.f + erff(v1 * INV_SQRT2));
                    __nv_bfloat162 h = __float22bfloat162_rn(make_float2(v0, v1));
                    *(__nv_bfloat162*)((__nv_bfloat16*)Cout + oidx) = h;
                } else {
                    if (res) { v0 += res[oidx]; v1 += res[oidx + 1]; }
                    *(float2*)((float*)Cout + oidx) = make_float2(v0, v1);
                }
            }
        }
    }
}

// ---------------------------------------------------------------------------
// Window attention (R3 version, conflict-free): one block per (window, head).
// ---------------------------------------------------------------------------
__global__ __launch_bounds__(256) void attn_kernel(
    const float* __restrict__ qkv, const float* __restrict__ rel_bias,
    const float* __restrict__ mask, float* __restrict__ out)
{
    int blk  = blockIdx.x;
    int win  = blk >> 3;
    int head = blk & 7;
    int tid  = threadIdx.x;

    __shared__ float qs[Nv * HDv];
    __shared__ float kst[HDv * Nv];
    __shared__ float vs[Nv * HDv];
    __shared__ float att[Nv * Nv];

    int base = win * Nv;
    for (int idx = tid; idx < Nv * HDv; idx += 256) {
        int n = idx >> 5, d = idx & 31;
        int row = (base + n) * (3 * Cv);
        int f   = head * HDv + d;
        qs[idx]         = qkv[row + f] * SCALEv;
        kst[d * Nv + n] = qkv[row + Cv + f];
        vs[idx]         = qkv[row + 2 * Cv + f];
    }
    __syncthreads();

    int wm = win % NWIN;
    for (int e = tid; e < Nv * Nv; e += 256) {
        int n = e / Nv, m = e % Nv;
        float s = 0.f;
        #pragma unroll
        for (int d = 0; d < HDv; d++)
            s = fmaf(qs[n * HDv + d], kst[d * Nv + m], s);
        int r1 = n / WSv, c1 = n % WSv;
        int r2 = m / WSv, c2 = m % WSv;
        int bi = (r1 - r2 + WSv - 1) * (2 * WSv - 1) + (c1 - c2 + WSv - 1);
        s += rel_bias[bi * NHv + head] + mask[wm * (Nv * Nv) + e];
        att[e] = s;
    }
    __syncthreads();

    if (tid < Nv) {
        float mx = -1e30f;
        #pragma unroll 7
        for (int m = 0; m < Nv; m++) mx = fmaxf(mx, att[tid * Nv + m]);
        float sum = 0.f;
        #pragma unroll 7
        for (int m = 0; m < Nv; m++) {
            float e2 = __expf(att[tid * Nv + m] - mx);
            att[tid * Nv + m] = e2;
            sum += e2;
        }
        float inv = 1.f / sum;
        #pragma unroll 7
        for (int m = 0; m < Nv; m++) att[tid * Nv + m] *= inv;
    }
    __syncthreads();

    for (int idx = tid; idx < Nv * HDv; idx += 256) {
        int n = idx >> 5, d = idx & 31;
        float s = 0.f;
        #pragma unroll 7
        for (int m = 0; m < Nv; m++)
            s = fmaf(att[n * Nv + m], vs[m * HDv + d], s);
        out[(size_t)(base + n) * Cv + head * HDv + d] = s;
    }
}

// ---------------------------------------------------------------------------
extern "C" void kernel_launch(void* const* d_in, const int* in_sizes, int n_in,
                              void* d_out, int out_size)
{
    const float* x       = (const float*)d_in[0];
    const float* mask    = (const float*)d_in[1];
    const float* norm1_g = (const float*)d_in[2];
    const float* norm1_b = (const float*)d_in[3];
    const float* qkv_w   = (const float*)d_in[4];
    const float* qkv_b   = (const float*)d_in[5];
    const float* rel_bias= (const float*)d_in[6];
    const float* proj_w  = (const float*)d_in[7];
    const float* proj_b  = (const float*)d_in[8];
    const float* norm2_g = (const float*)d_in[9];
    const float* norm2_b = (const float*)d_in[10];
    const float* fc1_w   = (const float*)d_in[11];
    const float* fc1_b   = (const float*)d_in[12];
    const float* fc2_w   = (const float*)d_in[13];
    const float* fc2_b   = (const float*)d_in[14];
    float* out = (float*)d_out;

    float *p_qkv, *p_atto, *p_x1, *p_mu1, *p_rs1, *p_mu2, *p_rs2;
    float *p_qkvwf, *p_qkvbf, *p_fc1wf, *p_fc1bf;
    __nv_bfloat16* p_hid;
    cudaGetSymbolAddress((void**)&p_qkv,   g_qkv);
    cudaGetSymbolAddress((void**)&p_atto,  g_atto);
    cudaGetSymbolAddress((void**)&p_x1,    g_x1);
    cudaGetSymbolAddress((void**)&p_hid,   g_hid);
    cudaGetSymbolAddress((void**)&p_mu1,   g_mu1);
    cudaGetSymbolAddress((void**)&p_rs1,   g_rs1);
    cudaGetSymbolAddress((void**)&p_mu2,   g_mu2);
    cudaGetSymbolAddress((void**)&p_rs2,   g_rs2);
    cudaGetSymbolAddress((void**)&p_qkvwf, g_qkvwf);
    cudaGetSymbolAddress((void**)&p_qkvbf, g_qkvbf);
    cudaGetSymbolAddress((void**)&p_fc1wf, g_fc1wf);
    cudaGetSymbolAddress((void**)&p_fc1bf, g_fc1bf);

    // 0. fold LN affine params into GEMM weights/bias
    fold_kernel<<<3 * Cv, 256>>>(qkv_w, qkv_b, norm1_g, norm1_b, p_qkvwf, p_qkvbf);
    fold_kernel<<<4 * Cv, 256>>>(fc1_w, fc1_b, norm2_g, norm2_b, p_fc1wf, p_fc1bf);

    // 1. LN1 stats (window-order indexed)
    ln_stats_kernel<<<TOK / 8, 256>>>(x, p_mu1, p_rs1, 1);

    // 2. QKV GEMM, fused LN1 (gather + normalize)
    {
        dim3 grid(3 * Cv / 128, TOK / 128);
        tf32_gemm_kernel<1, 0><<<grid, 256>>>(x, p_qkvwf, p_qkvbf, nullptr,
                                              p_qkv, p_mu1, p_rs1,
                                              TOK, 3 * Cv, Cv);
    }

    // 3. window attention
    attn_kernel<<<BW * NHv, 256>>>(p_qkv, rel_bias, mask, p_atto);

    // 4. proj GEMM, fused window-reverse + unshift + residual(x) -> x1
    {
        dim3 grid(Cv / 128, TOK / 128);
        tf32_gemm_kernel<0, 2><<<grid, 256>>>(p_atto, proj_w, proj_b, x,
                                              p_x1, nullptr, nullptr,
                                              TOK, Cv, Cv);
    }

    // 5. LN2 stats (identity order, over x1)
    ln_stats_kernel<<<TOK / 8, 256>>>(p_x1, p_mu2, p_rs2, 0);

    // 6. fc1 GEMM, fused LN2 + GELU, bf16 output
    {
        dim3 grid(4 * Cv / 128, TOK / 128);
        tf32_gemm_kernel<2, 1><<<grid, 256>>>(p_x1, p_fc1wf, p_fc1bf, nullptr,
                                              p_hid, p_mu2, p_rs2,
                                              TOK, 4 * Cv, Cv);
    }

    // 7. fc2 GEMM (bf16 A) + residual(x1) -> out
    {
        dim3 grid(Cv / 128, TOK / 128);
        tf32_gemm_kernel<3, 0><<<grid, 256>>>(p_hid, fc2_w, fc2_b, p_x1,
                                              out, nullptr, nullptr,
                                              TOK, Cv, 4 * Cv);
    }
}

// round 8
// speedup vs baseline: 1.1196x; 1.1196x over previous
#include <cuda_runtime.h>
#include <cuda_bf16.h>
#include <math.h>
#include <stdint.h>

// ---------------------------------------------------------------------------
// Swin Transformer block, B=16, H=W=56, C=256, NH=8, WS=7, SS=3, HD=32, N=49
// R7: cp.async 4-stage pipelined TF32 GEMM; LN fused via epilogue
//     compensation (colsum); conflict-free smem (stride-20 rows).
// ---------------------------------------------------------------------------

#define Bv    16
#define Hv    56
#define Wv    56
#define Cv    256
#define NHv   8
#define WSv   7
#define SSv   3
#define HDv   32
#define Nv    49
#define NWIN  64
#define BW    1024
#define TOK   50176
#define SCALEv 0.17677669529663687f

#define STAGES 4
#define SROW   20                       // floats per smem row (80B, 16B-aligned)
#define STAGE_FLOATS (128 * SROW)

// scratch
__device__ float g_qkv[TOK * 3 * Cv];
__device__ float g_atto[TOK * Cv];
__device__ float g_x1[TOK * Cv];
__device__ float g_hid[TOK * 4 * Cv];
__device__ float g_mu1[TOK], g_rs1[TOK];
__device__ float g_mu2[TOK], g_rs2[TOK];
__device__ float g_qkvwf[3 * Cv * Cv], g_qkvbf[3 * Cv], g_qkvcs[3 * Cv];
__device__ float g_fc1wf[4 * Cv * Cv], g_fc1bf[4 * Cv], g_fc1cs[4 * Cv];

// window-order token t -> source token in x (forward shift + partition)
__device__ __forceinline__ int win_src(int t) {
    int win = t / Nv, n = t % Nv;
    int b = win >> 6, w = win & 63;
    int i = (w >> 3) * WSv + n / WSv;
    int j = (w & 7) * WSv + n % WSv;
    int si = (i + SSv) % Hv;
    int sj = (j + SSv) % Wv;
    return b * (Hv * Wv) + si * Wv + sj;
}
// window-order row -> output token (window reverse + unshift)
__device__ __forceinline__ int inv_tok(int row) {
    int win = row / Nv, n = row % Nv;
    int b = win >> 6, w = win & 63;
    int p = (w >> 3) * WSv + n / WSv;
    int q = (w & 7) * WSv + n % WSv;
    int i = (p + SSv) % Hv;
    int j = (q + SSv) % Wv;
    return b * (Hv * Wv) + i * Wv + j;
}

// ---------------------------------------------------------------------------
// fold: Wg[n][k] = W[n][k]*g[k]; bg[n] = bias[n] + sum_k W[n][k]*beta[k];
//       cs[n] = sum_k Wg[n][k].    One block per output row n; K == 256.
// ---------------------------------------------------------------------------
__global__ __launch_bounds__(256) void fold_kernel(
    const float* __restrict__ W, const float* __restrict__ bias,
    const float* __restrict__ g, const float* __restrict__ be,
    float* __restrict__ Wg, float* __restrict__ bg, float* __restrict__ cs)
{
    int n = blockIdx.x, k = threadIdx.x;
    float w  = W[n * Cv + k];
    float wg = w * g[k];
    Wg[n * Cv + k] = wg;
    float p = w * be[k];
    float q = wg;
    #pragma unroll
    for (int o = 16; o > 0; o >>= 1) {
        p += __shfl_xor_sync(0xffffffffu, p, o);
        q += __shfl_xor_sync(0xffffffffu, q, o);
    }
    __shared__ float ws[8], wq[8];
    if ((k & 31) == 0) { ws[k >> 5] = p; wq[k >> 5] = q; }
    __syncthreads();
    if (k == 0) {
        float s = 0.f, s2 = 0.f;
        #pragma unroll
        for (int i = 0; i < 8; i++) { s += ws[i]; s2 += wq[i]; }
        bg[n] = bias[n] + s;
        cs[n] = s2;
    }
}

// ---------------------------------------------------------------------------
// per-token LN stats. warp per token, 8 tokens/block.
// mode 1: token index is window-order (gather via win_src); mode 0: identity.
// ---------------------------------------------------------------------------
__global__ __launch_bounds__(256) void ln_stats_kernel(
    const float* __restrict__ x, float* __restrict__ MU, float* __restrict__ RS,
    int mode)
{
    int warp = threadIdx.x >> 5, lane = threadIdx.x & 31;
    int t = blockIdx.x * 8 + warp;
    int src = mode ? win_src(t) : t;
    const float4* xr = (const float4*)(x + (size_t)src * Cv);
    float4 v0 = xr[lane], v1 = xr[lane + 32];
    float s  = v0.x + v0.y + v0.z + v0.w + v1.x + v1.y + v1.z + v1.w;
    float s2 = v0.x*v0.x + v0.y*v0.y + v0.z*v0.z + v0.w*v0.w
             + v1.x*v1.x + v1.y*v1.y + v1.z*v1.z + v1.w*v1.w;
    #pragma unroll
    for (int o = 16; o > 0; o >>= 1) {
        s  += __shfl_xor_sync(0xffffffffu, s,  o);
        s2 += __shfl_xor_sync(0xffffffffu, s2, o);
    }
    if (lane == 0) {
        float mu  = s * (1.f / Cv);
        float var = s2 * (1.f / Cv) - mu * mu;
        MU[t] = mu;
        RS[t] = rsqrtf(var + 1e-5f);
    }
}

// ---------------------------------------------------------------------------
// Pipelined TF32 GEMM.
// GATHER: A rows gathered via win_src.
// LNEPI : epilogue applies out = rs*acc - rs*mu*colsum[col] + bias[col].
// OMODE : 0 plain (+bias, +res same row); 1 GELU; 2 unshift remap + res.
// ---------------------------------------------------------------------------
__device__ __forceinline__ uint32_t smem_u32(const void* p) {
    uint32_t r;
    asm("{.reg .u64 t; cvta.to.shared.u64 t, %1; cvt.u32.u64 %0, t;}"
        : "=r"(r) : "l"(p));
    return r;
}
__device__ __forceinline__ void mma_tf32(float* c, const uint32_t* a, const uint32_t* b) {
    asm volatile(
        "mma.sync.aligned.m16n8k8.row.col.f32.tf32.tf32.f32 "
        "{%0,%1,%2,%3}, {%4,%5,%6,%7}, {%8,%9}, {%0,%1,%2,%3};"
        : "+f"(c[0]), "+f"(c[1]), "+f"(c[2]), "+f"(c[3])
        : "r"(a[0]), "r"(a[1]), "r"(a[2]), "r"(a[3]), "r"(b[0]), "r"(b[1]));
}

template<int GATHER, int LNEPI, int OMODE>
__global__ __launch_bounds__(256) void gemm_pipe(
    const float* __restrict__ A, const float* __restrict__ Wt,
    const float* __restrict__ bias, const float* __restrict__ colsum,
    const float* __restrict__ MU, const float* __restrict__ RS,
    const float* __restrict__ res, float* __restrict__ Cout,
    int M, int Nc, int K)
{
    extern __shared__ float sm[];
    float* AsBase = sm;
    float* BsBase = sm + STAGES * STAGE_FLOATS;

    int tid  = threadIdx.x;
    int warp = tid >> 5, lane = tid & 31;
    int wm   = (warp >> 2) * 64;
    int wn   = (warp & 3) * 32;
    int bm   = blockIdx.y * 128, bn = blockIdx.x * 128;

    // loader mapping: thread -> one A row + one B row, 2x16B chunks each
    int lr  = tid >> 1;
    int lc8 = (tid & 1) * 8;
    int at  = bm + lr;
    const float* arow = A  + (size_t)(GATHER ? win_src(at) : at) * K + lc8;
    const float* brow = Wt + (size_t)(bn + lr) * K + lc8;
    uint32_t sA = smem_u32(AsBase) + (uint32_t)(lr * SROW + lc8) * 4u;
    uint32_t sB = smem_u32(BsBase) + (uint32_t)(lr * SROW + lc8) * 4u;
    const uint32_t stageB = STAGE_FLOATS * 4u;

    float acc[4][4][4];
    #pragma unroll
    for (int mt = 0; mt < 4; mt++)
        #pragma unroll
        for (int nt = 0; nt < 4; nt++)
            #pragma unroll
            for (int i = 0; i < 4; i++) acc[mt][nt][i] = 0.f;

    const int KT = K / 16;

    auto issue = [&](int j) {
        uint32_t da = sA + (uint32_t)(j % STAGES) * stageB;
        uint32_t db = sB + (uint32_t)(j % STAGES) * stageB;
        const float* ga = arow + j * 16;
        const float* gb = brow + j * 16;
        asm volatile(
            "cp.async.ca.shared.global [%0], [%1], 16;\n"
            "cp.async.ca.shared.global [%2], [%3], 16;\n"
            "cp.async.ca.shared.global [%4], [%5], 16;\n"
            "cp.async.ca.shared.global [%6], [%7], 16;\n"
            :: "r"(da), "l"(ga), "r"(da + 16), "l"(ga + 4),
               "r"(db), "l"(gb), "r"(db + 16), "l"(gb + 4)
            : "memory");
        asm volatile("cp.async.commit_group;" ::: "memory");
    };

    #pragma unroll
    for (int j = 0; j < STAGES - 1; j++) issue(j);

    int qr = lane >> 2, qc = lane & 3;

    for (int it = 0; it < KT; it++) {
        asm volatile("cp.async.wait_group %0;" :: "n"(STAGES - 2) : "memory");
        __syncthreads();

        if (it + STAGES - 1 < KT) issue(it + STAGES - 1);
        else asm volatile("cp.async.commit_group;" ::: "memory");

        const float* a_s = AsBase + (it % STAGES) * STAGE_FLOATS;
        const float* b_s = BsBase + (it % STAGES) * STAGE_FLOATS;

        #pragma unroll
        for (int ks = 0; ks < 2; ks++) {
            int kb = ks * 8;
            uint32_t af[4][4], bf[4][2];
            #pragma unroll
            for (int mt = 0; mt < 4; mt++) {
                int m = wm + mt * 16 + qr;
                af[mt][0] = __float_as_uint(a_s[m * SROW + kb + qc]);
                af[mt][1] = __float_as_uint(a_s[(m + 8) * SROW + kb + qc]);
                af[mt][2] = __float_as_uint(a_s[m * SROW + kb + qc + 4]);
                af[mt][3] = __float_as_uint(a_s[(m + 8) * SROW + kb + qc + 4]);
            }
            #pragma unroll
            for (int nt = 0; nt < 4; nt++) {
                int n = wn + nt * 8 + qr;
                bf[nt][0] = __float_as_uint(b_s[n * SROW + kb + qc]);
                bf[nt][1] = __float_as_uint(b_s[n * SROW + kb + qc + 4]);
            }
            #pragma unroll
            for (int mt = 0; mt < 4; mt++)
                #pragma unroll
                for (int nt = 0; nt < 4; nt++)
                    mma_tf32(acc[mt][nt], af[mt], bf[nt]);
        }
    }
    asm volatile("cp.async.wait_all;" ::: "memory");

    // epilogue
    const float INV_SQRT2 = 0.70710678118654752f;
    #pragma unroll
    for (int mt = 0; mt < 4; mt++) {
        #pragma unroll
        for (int half = 0; half < 2; half++) {
            int row = bm + wm + mt * 16 + qr + half * 8;
            float mu = 0.f, rs = 1.f;
            if (LNEPI) { mu = MU[row]; rs = RS[row]; }
            int orow = (OMODE == 2) ? inv_tok(row) : row;
            #pragma unroll
            for (int nt = 0; nt < 4; nt++) {
                int col = bn + wn + nt * 8 + qc * 2;
                float v0 = acc[mt][nt][half * 2 + 0];
                float v1 = acc[mt][nt][half * 2 + 1];
                if (LNEPI) {
                    float mrs = mu * rs;
                    v0 = v0 * rs - mrs * colsum[col]     + bias[col];
                    v1 = v1 * rs - mrs * colsum[col + 1] + bias[col + 1];
                } else {
                    v0 += bias[col];
                    v1 += bias[col + 1];
                }
                if (OMODE == 1) {
                    v0 = 0.5f * v0 * (1.f + erff(v0 * INV_SQRT2));
                    v1 = 0.5f * v1 * (1.f + erff(v1 * INV_SQRT2));
                }
                size_t oidx = (size_t)orow * Nc + col;
                if ((OMODE == 0 || OMODE == 2) && res) {
                    v0 += res[oidx];
                    v1 += res[oidx + 1];
                }
                *(float2*)(Cout + oidx) = make_float2(v0, v1);
            }
        }
    }
}

// ---------------------------------------------------------------------------
// Window attention (conflict-free): one block per (window, head).
// ---------------------------------------------------------------------------
__global__ __launch_bounds__(256) void attn_kernel(
    const float* __restrict__ qkv, const float* __restrict__ rel_bias,
    const float* __restrict__ mask, float* __restrict__ out)
{
    int blk  = blockIdx.x;
    int win  = blk >> 3;
    int head = blk & 7;
    int tid  = threadIdx.x;

    __shared__ float qs[Nv * HDv];
    __shared__ float kst[HDv * Nv];
    __shared__ float vs[Nv * HDv];
    __shared__ float att[Nv * Nv];

    int base = win * Nv;
    for (int idx = tid; idx < Nv * HDv; idx += 256) {
        int n = idx >> 5, d = idx & 31;
        int row = (base + n) * (3 * Cv);
        int f   = head * HDv + d;
        qs[idx]         = qkv[row + f] * SCALEv;
        kst[d * Nv + n] = qkv[row + Cv + f];
        vs[idx]         = qkv[row + 2 * Cv + f];
    }
    __syncthreads();

    int wm = win % NWIN;
    for (int e = tid; e < Nv * Nv; e += 256) {
        int n = e / Nv, m = e % Nv;
        float s = 0.f;
        #pragma unroll
        for (int d = 0; d < HDv; d++)
            s = fmaf(qs[n * HDv + d], kst[d * Nv + m], s);
        int r1 = n / WSv, c1 = n % WSv;
        int r2 = m / WSv, c2 = m % WSv;
        int bi = (r1 - r2 + WSv - 1) * (2 * WSv - 1) + (c1 - c2 + WSv - 1);
        s += rel_bias[bi * NHv + head] + mask[wm * (Nv * Nv) + e];
        att[e] = s;
    }
    __syncthreads();

    if (tid < Nv) {
        float mx = -1e30f;
        #pragma unroll 7
        for (int m = 0; m < Nv; m++) mx = fmaxf(mx, att[tid * Nv + m]);
        float sum = 0.f;
        #pragma unroll 7
        for (int m = 0; m < Nv; m++) {
            float e2 = __expf(att[tid * Nv + m] - mx);
            att[tid * Nv + m] = e2;
            sum += e2;
        }
        float inv = 1.f / sum;
        #pragma unroll 7
        for (int m = 0; m < Nv; m++) att[tid * Nv + m] *= inv;
    }
    __syncthreads();

    for (int idx = tid; idx < Nv * HDv; idx += 256) {
        int n = idx >> 5, d = idx & 31;
        float s = 0.f;
        #pragma unroll 7
        for (int m = 0; m < Nv; m++)
            s = fmaf(att[n * Nv + m], vs[m * HDv + d], s);
        out[(size_t)(base + n) * Cv + head * HDv + d] = s;
    }
}

// ---------------------------------------------------------------------------
extern "C" void kernel_launch(void* const* d_in, const int* in_sizes, int n_in,
                              void* d_out, int out_size)
{
    const float* x       = (const float*)d_in[0];
    const float* mask    = (const float*)d_in[1];
    const float* norm1_g = (const float*)d_in[2];
    const float* norm1_b = (const float*)d_in[3];
    const float* qkv_w   = (const float*)d_in[4];
    const float* qkv_b   = (const float*)d_in[5];
    const float* rel_bias= (const float*)d_in[6];
    const float* proj_w  = (const float*)d_in[7];
    const float* proj_b  = (const float*)d_in[8];
    const float* norm2_g = (const float*)d_in[9];
    const float* norm2_b = (const float*)d_in[10];
    const float* fc1_w   = (const float*)d_in[11];
    const float* fc1_b   = (const float*)d_in[12];
    const float* fc2_w   = (const float*)d_in[13];
    const float* fc2_b   = (const float*)d_in[14];
    float* out = (float*)d_out;

    float *p_qkv, *p_atto, *p_x1, *p_hid;
    float *p_mu1, *p_rs1, *p_mu2, *p_rs2;
    float *p_qkvwf, *p_qkvbf, *p_qkvcs, *p_fc1wf, *p_fc1bf, *p_fc1cs;
    cudaGetSymbolAddress((void**)&p_qkv,   g_qkv);
    cudaGetSymbolAddress((void**)&p_atto,  g_atto);
    cudaGetSymbolAddress((void**)&p_x1,    g_x1);
    cudaGetSymbolAddress((void**)&p_hid,   g_hid);
    cudaGetSymbolAddress((void**)&p_mu1,   g_mu1);
    cudaGetSymbolAddress((void**)&p_rs1,   g_rs1);
    cudaGetSymbolAddress((void**)&p_mu2,   g_mu2);
    cudaGetSymbolAddress((void**)&p_rs2,   g_rs2);
    cudaGetSymbolAddress((void**)&p_qkvwf, g_qkvwf);
    cudaGetSymbolAddress((void**)&p_qkvbf, g_qkvbf);
    cudaGetSymbolAddress((void**)&p_qkvcs, g_qkvcs);
    cudaGetSymbolAddress((void**)&p_fc1wf, g_fc1wf);
    cudaGetSymbolAddress((void**)&p_fc1bf, g_fc1bf);
    cudaGetSymbolAddress((void**)&p_fc1cs, g_fc1cs);

    const int SMEM = STAGES * 2 * STAGE_FLOATS * 4;   // 81920 B
    static int attr_done = 0;
    if (!attr_done) {
        cudaFuncSetAttribute(gemm_pipe<1,1,0>, cudaFuncAttributeMaxDynamicSharedMemorySize, SMEM);
        cudaFuncSetAttribute(gemm_pipe<0,0,2>, cudaFuncAttributeMaxDynamicSharedMemorySize, SMEM);
        cudaFuncSetAttribute(gemm_pipe<0,1,1>, cudaFuncAttributeMaxDynamicSharedMemorySize, SMEM);
        cudaFuncSetAttribute(gemm_pipe<0,0,0>, cudaFuncAttributeMaxDynamicSharedMemorySize, SMEM);
        attr_done = 1;
    }

    // 0. fold LN affine params into GEMM weights/bias (+ column sums)
    fold_kernel<<<3 * Cv, 256>>>(qkv_w, qkv_b, norm1_g, norm1_b, p_qkvwf, p_qkvbf, p_qkvcs);
    fold_kernel<<<4 * Cv, 256>>>(fc1_w, fc1_b, norm2_g, norm2_b, p_fc1wf, p_fc1bf, p_fc1cs);

    // 1. LN1 stats (window-order indexed)
    ln_stats_kernel<<<TOK / 8, 256>>>(x, p_mu1, p_rs1, 1);

    // 2. QKV GEMM: gathered A rows, LN applied in epilogue
    {
        dim3 grid(3 * Cv / 128, TOK / 128);
        gemm_pipe<1,1,0><<<grid, 256, SMEM>>>(x, p_qkvwf, p_qkvbf, p_qkvcs,
                                              p_mu1, p_rs1, nullptr, p_qkv,
                                              TOK, 3 * Cv, Cv);
    }

    // 3. window attention
    attn_kernel<<<BW * NHv, 256>>>(p_qkv, rel_bias, mask, p_atto);

    // 4. proj GEMM, fused window-reverse + unshift + residual(x) -> x1
    {
        dim3 grid(Cv / 128, TOK / 128);
        gemm_pipe<0,0,2><<<grid, 256, SMEM>>>(p_atto, proj_w, proj_b, nullptr,
                                              nullptr, nullptr, x, p_x1,
                                              TOK, Cv, Cv);
    }

    // 5. LN2 stats (identity order, over x1)
    ln_stats_kernel<<<TOK / 8, 256>>>(p_x1, p_mu2, p_rs2, 0);

    // 6. fc1 GEMM, LN2 in epilogue + GELU -> hid (fp32)
    {
        dim3 grid(4 * Cv / 128, TOK / 128);
        gemm_pipe<0,1,1><<<grid, 256, SMEM>>>(p_x1, p_fc1wf, p_fc1bf, p_fc1cs,
                                              p_mu2, p_rs2, nullptr, p_hid,
                                              TOK, 4 * Cv, Cv);
    }

    // 7. fc2 GEMM + residual(x1) -> out
    {
        dim3 grid(Cv / 128, TOK / 128);
        gemm_pipe<0,0,0><<<grid, 256, SMEM>>>(p_hid, fc2_w, fc2_b, nullptr,
                                              nullptr, nullptr, p_x1, out,
                                              TOK, Cv, 4 * Cv);
    }
}

// round 10
// speedup vs baseline: 1.6969x; 1.5157x over previous
#include <cuda_runtime.h>
#include <cuda_fp16.h>
#include <math.h>
#include <stdint.h>

// ---------------------------------------------------------------------------
// Swin Transformer block, B=16, H=W=56, C=256, NH=8, WS=7, SS=3, HD=32, N=49
// R8: FP16 HMMA m16n8k16 GEMMs with ldmatrix fragments, fp32 accumulate.
//     Residual path fp32; activations between GEMMs fp16.
// ---------------------------------------------------------------------------

#define Bv    16
#define Hv    56
#define Wv    56
#define Cv    256
#define NHv   8
#define WSv   7
#define SSv   3
#define HDv   32
#define Nv    49
#define NWIN  64
#define BW    1024
#define TOK   50176
#define SCALEv 0.17677669529663687f

#define STG    3
#define SROWH  40                   // halves per smem row (80 B)
#define STAGE_H (128 * SROWH)       // halves per stage per matrix

// scratch (16B-aligned for cp.async / vector access)
__device__ __align__(256) __half g_xh[TOK * Cv];
__device__ __align__(256) __half g_qkvh[TOK * 3 * Cv];
__device__ __align__(256) __half g_attoh[TOK * Cv];
__device__ __align__(256) float  g_x1[TOK * Cv];
__device__ __align__(256) __half g_x1h[TOK * Cv];
__device__ __align__(256) __half g_hidh[TOK * 4 * Cv];
__device__ float g_mu1[TOK], g_rs1[TOK], g_mu2[TOK], g_rs2[TOK];
__device__ __align__(256) __half g_qkvwh[3 * Cv * Cv];
__device__ __align__(256) __half g_fc1wh[4 * Cv * Cv];
__device__ __align__(256) __half g_projwh[Cv * Cv];
__device__ __align__(256) __half g_fc2wh[Cv * 4 * Cv];
__device__ float g_qkvbf[3 * Cv], g_qkvcs[3 * Cv];
__device__ float g_fc1bf[4 * Cv], g_fc1cs[4 * Cv];

// window-order token t -> source token in x (forward shift + partition)
__device__ __forceinline__ int win_src(int t) {
    int win = t / Nv, n = t % Nv;
    int b = win >> 6, w = win & 63;
    int i = (w >> 3) * WSv + n / WSv;
    int j = (w & 7) * WSv + n % WSv;
    int si = (i + SSv) % Hv;
    int sj = (j + SSv) % Wv;
    return b * (Hv * Wv) + si * Wv + sj;
}
// window-order row -> output token (window reverse + unshift)
__device__ __forceinline__ int inv_tok(int row) {
    int win = row / Nv, n = row % Nv;
    int b = win >> 6, w = win & 63;
    int p = (w >> 3) * WSv + n / WSv;
    int q = (w & 7) * WSv + n % WSv;
    int i = (p + SSv) % Hv;
    int j = (q + SSv) % Wv;
    return b * (Hv * Wv) + i * Wv + j;
}

// ---------------------------------------------------------------------------
// fold (fp16 weights): Wh[n][k] = h(W*g); bg[n] = bias + sum W*beta;
// cs[n] = sum float(Wh[n][k])  (exact wrt stored fp16 weights).
// ---------------------------------------------------------------------------
__global__ __launch_bounds__(256) void fold_h_kernel(
    const float* __restrict__ W, const float* __restrict__ bias,
    const float* __restrict__ g, const float* __restrict__ be,
    __half* __restrict__ Wh, float* __restrict__ bg, float* __restrict__ cs)
{
    int n = blockIdx.x, k = threadIdx.x;
    float w = W[n * Cv + k];
    __half wh = __float2half(w * g[k]);
    Wh[n * Cv + k] = wh;
    float q = __half2float(wh);
    float p = w * be[k];
    #pragma unroll
    for (int o = 16; o > 0; o >>= 1) {
        p += __shfl_xor_sync(0xffffffffu, p, o);
        q += __shfl_xor_sync(0xffffffffu, q, o);
    }
    __shared__ float ws[8], wq[8];
    if ((k & 31) == 0) { ws[k >> 5] = p; wq[k >> 5] = q; }
    __syncthreads();
    if (k == 0) {
        float s = 0.f, s2 = 0.f;
        #pragma unroll
        for (int i = 0; i < 8; i++) { s += ws[i]; s2 += wq[i]; }
        bg[n] = bias[n] + s;
        cs[n] = s2;
    }
}

__global__ __launch_bounds__(256) void w2h_kernel(
    const float* __restrict__ W, __half* __restrict__ Wh, int n)
{
    int i = blockIdx.x * 256 + threadIdx.x;
    if (i < n) Wh[i] = __float2half(W[i]);
}

// ---------------------------------------------------------------------------
// per-token LN stats; optionally emits fp16 copy of the (gathered) row.
// mode 1: window-order gather; mode 0: identity.
// ---------------------------------------------------------------------------
__global__ __launch_bounds__(256) void ln_stats_kernel(
    const float* __restrict__ x, float* __restrict__ MU, float* __restrict__ RS,
    __half* __restrict__ XH, int mode)
{
    int warp = threadIdx.x >> 5, lane = threadIdx.x & 31;
    int t = blockIdx.x * 8 + warp;
    int src = mode ? win_src(t) : t;
    const float4* xr = (const float4*)(x + (size_t)src * Cv);
    float4 v0 = xr[lane], v1 = xr[lane + 32];
    float s  = v0.x + v0.y + v0.z + v0.w + v1.x + v1.y + v1.z + v1.w;
    float s2 = v0.x*v0.x + v0.y*v0.y + v0.z*v0.z + v0.w*v0.w
             + v1.x*v1.x + v1.y*v1.y + v1.z*v1.z + v1.w*v1.w;
    #pragma unroll
    for (int o = 16; o > 0; o >>= 1) {
        s  += __shfl_xor_sync(0xffffffffu, s,  o);
        s2 += __shfl_xor_sync(0xffffffffu, s2, o);
    }
    if (XH) {
        __half2* hr = (__half2*)(XH + (size_t)t * Cv);
        hr[lane * 2]      = __floats2half2_rn(v0.x, v0.y);
        hr[lane * 2 + 1]  = __floats2half2_rn(v0.z, v0.w);
        hr[64 + lane * 2]     = __floats2half2_rn(v1.x, v1.y);
        hr[64 + lane * 2 + 1] = __floats2half2_rn(v1.z, v1.w);
    }
    if (lane == 0) {
        float mu  = s * (1.f / Cv);
        float var = s2 * (1.f / Cv) - mu * mu;
        MU[t] = mu;
        RS[t] = rsqrtf(var + 1e-5f);
    }
}

// ---------------------------------------------------------------------------
// FP16 HMMA GEMM, cp.async 3-stage, ldmatrix fragments.
// LNEPI : out = rs*acc - rs*mu*colsum[col] + bias[col]  (else acc + bias)
// OMODE : 0 -> fp16 out; 1 -> GELU, fp16 out; 2 -> unshift remap + res(fp32),
//         writes fp32 Out AND fp16 Out2; 3 -> +res(fp32), fp32 out.
// ---------------------------------------------------------------------------
__device__ __forceinline__ uint32_t smem_u32(const void* p) {
    uint32_t r;
    asm("{.reg .u64 t; cvta.to.shared.u64 t, %1; cvt.u32.u64 %0, t;}"
        : "=r"(r) : "l"(p));
    return r;
}
__device__ __forceinline__ void ldm_x4(uint32_t* r, uint32_t addr) {
    asm volatile("ldmatrix.sync.aligned.m8n8.x4.shared.b16 {%0,%1,%2,%3}, [%4];"
        : "=r"(r[0]), "=r"(r[1]), "=r"(r[2]), "=r"(r[3]) : "r"(addr));
}
__device__ __forceinline__ void mma_f16(float* c, const uint32_t* a, const uint32_t* b) {
    asm volatile(
        "mma.sync.aligned.m16n8k16.row.col.f32.f16.f16.f32 "
        "{%0,%1,%2,%3}, {%4,%5,%6,%7}, {%8,%9}, {%0,%1,%2,%3};"
        : "+f"(c[0]), "+f"(c[1]), "+f"(c[2]), "+f"(c[3])
        : "r"(a[0]), "r"(a[1]), "r"(a[2]), "r"(a[3]), "r"(b[0]), "r"(b[1]));
}

template<int LNEPI, int OMODE>
__global__ __launch_bounds__(256) void hgemm(
    const __half* __restrict__ A, const __half* __restrict__ Wh,
    const float* __restrict__ bias, const float* __restrict__ colsum,
    const float* __restrict__ MU, const float* __restrict__ RS,
    const float* __restrict__ res, void* __restrict__ Out,
    void* __restrict__ Out2, int M, int Nc, int K)
{
    extern __shared__ __half smh[];
    __half* As = smh;
    __half* Bs = smh + STG * STAGE_H;

    int tid  = threadIdx.x;
    int warp = tid >> 5, lane = tid & 31;
    int wm   = (warp >> 2) * 64;
    int wn   = (warp & 3) * 32;
    int bm   = blockIdx.y * 128, bn = blockIdx.x * 128;

    // loader: thread -> 1 A row + 1 B row, 2x16B chunks each (32 halves/tile)
    int lr = tid >> 1;
    int hc = (tid & 1) * 16;
    const __half* ga = A  + (size_t)(bm + lr) * K + hc;
    const __half* gb = Wh + (size_t)(bn + lr) * K + hc;
    uint32_t sAbase = smem_u32(As);
    uint32_t sBbase = smem_u32(Bs);
    uint32_t sA = sAbase + (uint32_t)(lr * SROWH + hc) * 2u;
    uint32_t sB = sBbase + (uint32_t)(lr * SROWH + hc) * 2u;
    const uint32_t stgB = STAGE_H * 2u;

    float acc[4][4][4];
    #pragma unroll
    for (int mt = 0; mt < 4; mt++)
        #pragma unroll
        for (int nt = 0; nt < 4; nt++)
            #pragma unroll
            for (int i = 0; i < 4; i++) acc[mt][nt][i] = 0.f;

    const int KT = K / 32;

    auto issue = [&](int j) {
        uint32_t da = sA + (uint32_t)(j % STG) * stgB;
        uint32_t db = sB + (uint32_t)(j % STG) * stgB;
        const __half* a0 = ga + (size_t)j * 32;
        const __half* b0 = gb + (size_t)j * 32;
        asm volatile(
            "cp.async.ca.shared.global [%0], [%1], 16;\n"
            "cp.async.ca.shared.global [%2], [%3], 16;\n"
            "cp.async.ca.shared.global [%4], [%5], 16;\n"
            "cp.async.ca.shared.global [%6], [%7], 16;\n"
            :: "r"(da), "l"(a0), "r"(da + 16), "l"(a0 + 8),
               "r"(db), "l"(b0), "r"(db + 16), "l"(b0 + 8)
            : "memory");
        asm volatile("cp.async.commit_group;" ::: "memory");
    };

    #pragma unroll
    for (int j = 0; j < STG - 1; j++) issue(j);

    // ldmatrix lane addressing
    int rla = lane & 15;
    int cla = (lane & 16) >> 1;               // 0 or 8 (halves)
    int rlb = (lane & 7) | ((lane & 16) >> 1);
    int clb = lane & 8;                       // 0 or 8 (halves)

    for (int it = 0; it < KT; it++) {
        asm volatile("cp.async.wait_group %0;" :: "n"(STG - 2) : "memory");
        __syncthreads();

        if (it + STG - 1 < KT) issue(it + STG - 1);
        else asm volatile("cp.async.commit_group;" ::: "memory");

        uint32_t baseA = sAbase + (uint32_t)(it % STG) * stgB;
        uint32_t baseB = sBbase + (uint32_t)(it % STG) * stgB;

        #pragma unroll
        for (int ks = 0; ks < 2; ks++) {
            int kb = ks * 16;
            uint32_t a[4][4], bq[2][4];
            #pragma unroll
            for (int mt = 0; mt < 4; mt++)
                ldm_x4(a[mt], baseA + (uint32_t)((wm + mt * 16 + rla) * SROWH + kb + cla) * 2u);
            #pragma unroll
            for (int p = 0; p < 2; p++)
                ldm_x4(bq[p], baseB + (uint32_t)((wn + p * 16 + rlb) * SROWH + kb + clb) * 2u);
            #pragma unroll
            for (int mt = 0; mt < 4; mt++)
                #pragma unroll
                for (int nt = 0; nt < 4; nt++)
                    mma_f16(acc[mt][nt], a[mt], &bq[nt >> 1][(nt & 1) * 2]);
        }
    }
    asm volatile("cp.async.wait_all;" ::: "memory");

    // epilogue
    const float INV_SQRT2 = 0.70710678118654752f;
    int qr = lane >> 2, qc = lane & 3;
    #pragma unroll
    for (int mt = 0; mt < 4; mt++) {
        #pragma unroll
        for (int half = 0; half < 2; half++) {
            int row = bm + wm + mt * 16 + qr + half * 8;
            float mu = 0.f, rs = 1.f;
            if (LNEPI) { mu = MU[row]; rs = RS[row]; }
            int orow = (OMODE == 2) ? inv_tok(row) : row;
            #pragma unroll
            for (int nt = 0; nt < 4; nt++) {
                int col = bn + wn + nt * 8 + qc * 2;
                float v0 = acc[mt][nt][half * 2 + 0];
                float v1 = acc[mt][nt][half * 2 + 1];
                if (LNEPI) {
                    float mrs = mu * rs;
                    v0 = v0 * rs - mrs * colsum[col]     + bias[col];
                    v1 = v1 * rs - mrs * colsum[col + 1] + bias[col + 1];
                } else {
                    v0 += bias[col];
                    v1 += bias[col + 1];
                }
                size_t oidx = (size_t)orow * Nc + col;
                if (OMODE == 0) {
                    *(__half2*)((__half*)Out + oidx) = __floats2half2_rn(v0, v1);
                } else if (OMODE == 1) {
                    v0 = 0.5f * v0 * (1.f + erff(v0 * INV_SQRT2));
                    v1 = 0.5f * v1 * (1.f + erff(v1 * INV_SQRT2));
                    *(__half2*)((__half*)Out + oidx) = __floats2half2_rn(v0, v1);
                } else if (OMODE == 2) {
                    v0 += res[oidx];
                    v1 += res[oidx + 1];
                    *(float2*)((float*)Out + oidx) = make_float2(v0, v1);
                    *(__half2*)((__half*)Out2 + oidx) = __floats2half2_rn(v0, v1);
                } else { // 3
                    v0 += res[oidx];
                    v1 += res[oidx + 1];
                    *(float2*)((float*)Out + oidx) = make_float2(v0, v1);
                }
            }
        }
    }
}

// ---------------------------------------------------------------------------
// Window attention (conflict-free), fp16 in/out, fp32 compute.
// ---------------------------------------------------------------------------
__global__ __launch_bounds__(256) void attn_kernel(
    const __half* __restrict__ qkv, const float* __restrict__ rel_bias,
    const float* __restrict__ mask, __half* __restrict__ out)
{
    int blk  = blockIdx.x;
    int win  = blk >> 3;
    int head = blk & 7;
    int tid  = threadIdx.x;

    __shared__ float qs[Nv * HDv];
    __shared__ float kst[HDv * Nv];
    __shared__ float vs[Nv * HDv];
    __shared__ float att[Nv * Nv];

    int base = win * Nv;
    for (int idx = tid; idx < Nv * HDv; idx += 256) {
        int n = idx >> 5, d = idx & 31;
        int row = (base + n) * (3 * Cv);
        int f   = head * HDv + d;
        qs[idx]         = __half2float(qkv[row + f]) * SCALEv;
        kst[d * Nv + n] = __half2float(qkv[row + Cv + f]);
        vs[idx]         = __half2float(qkv[row + 2 * Cv + f]);
    }
    __syncthreads();

    int wm = win % NWIN;
    for (int e = tid; e < Nv * Nv; e += 256) {
        int n = e / Nv, m = e % Nv;
        float s = 0.f;
        #pragma unroll
        for (int d = 0; d < HDv; d++)
            s = fmaf(qs[n * HDv + d], kst[d * Nv + m], s);
        int r1 = n / WSv, c1 = n % WSv;
        int r2 = m / WSv, c2 = m % WSv;
        int bi = (r1 - r2 + WSv - 1) * (2 * WSv - 1) + (c1 - c2 + WSv - 1);
        s += rel_bias[bi * NHv + head] + mask[wm * (Nv * Nv) + e];
        att[e] = s;
    }
    __syncthreads();

    if (tid < Nv) {
        float mx = -1e30f;
        #pragma unroll 7
        for (int m = 0; m < Nv; m++) mx = fmaxf(mx, att[tid * Nv + m]);
        float sum = 0.f;
        #pragma unroll 7
        for (int m = 0; m < Nv; m++) {
            float e2 = __expf(att[tid * Nv + m] - mx);
            att[tid * Nv + m] = e2;
            sum += e2;
        }
        float inv = 1.f / sum;
        #pragma unroll 7
        for (int m = 0; m < Nv; m++) att[tid * Nv + m] *= inv;
    }
    __syncthreads();

    for (int idx = tid; idx < Nv * HDv; idx += 256) {
        int n = idx >> 5, d = idx & 31;
        float s = 0.f;
        #pragma unroll 7
        for (int m = 0; m < Nv; m++)
            s = fmaf(att[n * Nv + m], vs[m * HDv + d], s);
        out[(size_t)(base + n) * Cv + head * HDv + d] = __float2half(s);
    }
}

// ---------------------------------------------------------------------------
extern "C" void kernel_launch(void* const* d_in, const int* in_sizes, int n_in,
                              void* d_out, int out_size)
{
    const float* x       = (const float*)d_in[0];
    const float* mask    = (const float*)d_in[1];
    const float* norm1_g = (const float*)d_in[2];
    const float* norm1_b = (const float*)d_in[3];
    const float* qkv_w   = (const float*)d_in[4];
    const float* qkv_b   = (const float*)d_in[5];
    const float* rel_bias= (const float*)d_in[6];
    const float* proj_w  = (const float*)d_in[7];
    const float* proj_b  = (const float*)d_in[8];
    const float* norm2_g = (const float*)d_in[9];
    const float* norm2_b = (const float*)d_in[10];
    const float* fc1_w   = (const float*)d_in[11];
    const float* fc1_b   = (const float*)d_in[12];
    const float* fc2_w   = (const float*)d_in[13];
    const float* fc2_b   = (const float*)d_in[14];
    float* out = (float*)d_out;

    __half *p_xh, *p_qkvh, *p_attoh, *p_x1h, *p_hidh;
    __half *p_qkvwh, *p_fc1wh, *p_projwh, *p_fc2wh;
    float *p_x1, *p_mu1, *p_rs1, *p_mu2, *p_rs2;
    float *p_qkvbf, *p_qkvcs, *p_fc1bf, *p_fc1cs;
    cudaGetSymbolAddress((void**)&p_xh,     g_xh);
    cudaGetSymbolAddress((void**)&p_qkvh,   g_qkvh);
    cudaGetSymbolAddress((void**)&p_attoh,  g_attoh);
    cudaGetSymbolAddress((void**)&p_x1,     g_x1);
    cudaGetSymbolAddress((void**)&p_x1h,    g_x1h);
    cudaGetSymbolAddress((void**)&p_hidh,   g_hidh);
    cudaGetSymbolAddress((void**)&p_mu1,    g_mu1);
    cudaGetSymbolAddress((void**)&p_rs1,    g_rs1);
    cudaGetSymbolAddress((void**)&p_mu2,    g_mu2);
    cudaGetSymbolAddress((void**)&p_rs2,    g_rs2);
    cudaGetSymbolAddress((void**)&p_qkvwh,  g_qkvwh);
    cudaGetSymbolAddress((void**)&p_fc1wh,  g_fc1wh);
    cudaGetSymbolAddress((void**)&p_projwh, g_projwh);
    cudaGetSymbolAddress((void**)&p_fc2wh,  g_fc2wh);
    cudaGetSymbolAddress((void**)&p_qkvbf,  g_qkvbf);
    cudaGetSymbolAddress((void**)&p_qkvcs,  g_qkvcs);
    cudaGetSymbolAddress((void**)&p_fc1bf,  g_fc1bf);
    cudaGetSymbolAddress((void**)&p_fc1cs,  g_fc1cs);

    const int SMEM = STG * 2 * STAGE_H * 2;   // 61440 B
    static int attr_done = 0;
    if (!attr_done) {
        cudaFuncSetAttribute(hgemm<1,0>, cudaFuncAttributeMaxDynamicSharedMemorySize, SMEM);
        cudaFuncSetAttribute(hgemm<0,2>, cudaFuncAttributeMaxDynamicSharedMemorySize, SMEM);
        cudaFuncSetAttribute(hgemm<1,1>, cudaFuncAttributeMaxDynamicSharedMemorySize, SMEM);
        cudaFuncSetAttribute(hgemm<0,3>, cudaFuncAttributeMaxDynamicSharedMemorySize, SMEM);
        attr_done = 1;
    }

    // 0. weight prep
    fold_h_kernel<<<3 * Cv, 256>>>(qkv_w, qkv_b, norm1_g, norm1_b, p_qkvwh, p_qkvbf, p_qkvcs);
    fold_h_kernel<<<4 * Cv, 256>>>(fc1_w, fc1_b, norm2_g, norm2_b, p_fc1wh, p_fc1bf, p_fc1cs);
    w2h_kernel<<<(Cv * Cv + 255) / 256, 256>>>(proj_w, p_projwh, Cv * Cv);
    w2h_kernel<<<(Cv * 4 * Cv + 255) / 256, 256>>>(fc2_w, p_fc2wh, Cv * 4 * Cv);

    // 1. LN1 stats + fp16 gathered copy of x (window order)
    ln_stats_kernel<<<TOK / 8, 256>>>(x, p_mu1, p_rs1, p_xh, 1);

    // 2. QKV GEMM (LN in epilogue) -> qkv fp16
    {
        dim3 grid(3 * Cv / 128, TOK / 128);
        hgemm<1,0><<<grid, 256, SMEM>>>(p_xh, p_qkvwh, p_qkvbf, p_qkvcs,
                                        p_mu1, p_rs1, nullptr, p_qkvh, nullptr,
                                        TOK, 3 * Cv, Cv);
    }

    // 3. window attention -> atto fp16
    attn_kernel<<<BW * NHv, 256>>>(p_qkvh, rel_bias, mask, p_attoh);

    // 4. proj GEMM + window-reverse/unshift + residual(x) -> x1 fp32 + fp16
    {
        dim3 grid(Cv / 128, TOK / 128);
        hgemm<0,2><<<grid, 256, SMEM>>>(p_attoh, p_projwh, proj_b, nullptr,
                                        nullptr, nullptr, x, p_x1, p_x1h,
                                        TOK, Cv, Cv);
    }

    // 5. LN2 stats
    ln_stats_kernel<<<TOK / 8, 256>>>(p_x1, p_mu2, p_rs2, nullptr, 0);

    // 6. fc1 GEMM (LN2 epilogue) + GELU -> hid fp16
    {
        dim3 grid(4 * Cv / 128, TOK / 128);
        hgemm<1,1><<<grid, 256, SMEM>>>(p_x1h, p_fc1wh, p_fc1bf, p_fc1cs,
                                        p_mu2, p_rs2, nullptr, p_hidh, nullptr,
                                        TOK, 4 * Cv, Cv);
    }

    // 7. fc2 GEMM + residual(x1) -> out fp32
    {
        dim3 grid(Cv / 128, TOK / 128);
        hgemm<0,3><<<grid, 256, SMEM>>>(p_hidh, p_fc2wh, fc2_b, nullptr,
                                        nullptr, nullptr, p_x1, out, nullptr,
                                        TOK, Cv, 4 * Cv);
    }
}

// round 12
// speedup vs baseline: 2.5988x; 1.5315x over previous
#include <cuda_runtime.h>
#include <cuda_fp16.h>
#include <math.h>
#include <stdint.h>

// ---------------------------------------------------------------------------
// Swin Transformer block, B=16, H=W=56, C=256, NH=8, WS=7, SS=3, HD=32, N=49
// R10: tensor-core attention (HMMA + in-register softmax), scale folded into
//      QKV weights, combined mask+rel_bias table. GEMMs as R8.
// ---------------------------------------------------------------------------

#define Bv    16
#define Hv    56
#define Wv    56
#define Cv    256
#define NHv   8
#define WSv   7
#define SSv   3
#define HDv   32
#define Nv    49
#define NWIN  64
#define BW    1024
#define TOK   50176
#define SCALEv 0.17677669529663687f

#define STG    3
#define SROWH  40
#define STAGE_H (128 * SROWH)

// scratch
__device__ __align__(256) __half g_xh[TOK * Cv];
__device__ __align__(256) __half g_qkvh[TOK * 3 * Cv];
__device__ __align__(256) __half g_attoh[TOK * Cv];
__device__ __align__(256) float  g_x1[TOK * Cv];
__device__ __align__(256) __half g_x1h[TOK * Cv];
__device__ __align__(256) __half g_hidh[TOK * 4 * Cv];
__device__ float g_mu1[TOK], g_rs1[TOK], g_mu2[TOK], g_rs2[TOK];
__device__ __align__(256) __half g_qkvwh[3 * Cv * Cv];
__device__ __align__(256) __half g_fc1wh[4 * Cv * Cv];
__device__ __align__(256) __half g_projwh[Cv * Cv];
__device__ __align__(256) __half g_fc2wh[Cv * 4 * Cv];
__device__ float g_qkvbf[3 * Cv], g_qkvcs[3 * Cv];
__device__ float g_fc1bf[4 * Cv], g_fc1cs[4 * Cv];
__device__ __align__(256) __half g_bias2[NWIN * NHv * 64 * 64];   // 4 MB

__device__ __forceinline__ int win_src(int t) {
    int win = t / Nv, n = t % Nv;
    int b = win >> 6, w = win & 63;
    int i = (w >> 3) * WSv + n / WSv;
    int j = (w & 7) * WSv + n % WSv;
    int si = (i + SSv) % Hv;
    int sj = (j + SSv) % Wv;
    return b * (Hv * Wv) + si * Wv + sj;
}
__device__ __forceinline__ int inv_tok(int row) {
    int win = row / Nv, n = row % Nv;
    int b = win >> 6, w = win & 63;
    int p = (w >> 3) * WSv + n / WSv;
    int q = (w & 7) * WSv + n % WSv;
    int i = (p + SSv) % Hv;
    int j = (q + SSv) % Wv;
    return b * (Hv * Wv) + i * Wv + j;
}

// ---------------------------------------------------------------------------
// fold (fp16 weights), optional per-row extra scale for rows < scale_rows
// (used to fold the attention softmax scale into Q rows of the QKV weight).
// ---------------------------------------------------------------------------
__global__ __launch_bounds__(256) void fold_h_kernel(
    const float* __restrict__ W, const float* __restrict__ bias,
    const float* __restrict__ g, const float* __restrict__ be,
    __half* __restrict__ Wh, float* __restrict__ bg, float* __restrict__ cs,
    int scale_rows)
{
    int n = blockIdx.x, k = threadIdx.x;
    float sc = (n < scale_rows) ? SCALEv : 1.f;
    float w = W[n * Cv + k];
    __half wh = __float2half(w * g[k] * sc);
    Wh[n * Cv + k] = wh;
    float q = __half2float(wh);
    float p = w * be[k];
    #pragma unroll
    for (int o = 16; o > 0; o >>= 1) {
        p += __shfl_xor_sync(0xffffffffu, p, o);
        q += __shfl_xor_sync(0xffffffffu, q, o);
    }
    __shared__ float ws[8], wq[8];
    if ((k & 31) == 0) { ws[k >> 5] = p; wq[k >> 5] = q; }
    __syncthreads();
    if (k == 0) {
        float s = 0.f, s2 = 0.f;
        #pragma unroll
        for (int i = 0; i < 8; i++) { s += ws[i]; s2 += wq[i]; }
        bg[n] = (bias[n] + s) * sc;
        cs[n] = s2;
    }
}

__global__ __launch_bounds__(256) void w2h_kernel(
    const float* __restrict__ W, __half* __restrict__ Wh, int n)
{
    int i = blockIdx.x * 256 + threadIdx.x;
    if (i < n) Wh[i] = __float2half(W[i]);
}

// ---------------------------------------------------------------------------
// bias2[wm][h][r][c] = rel_bias + mask (valid) else -30000.  64x64 padded.
// ---------------------------------------------------------------------------
__global__ __launch_bounds__(256) void bias2_kernel(
    const float* __restrict__ rel_bias, const float* __restrict__ mask,
    __half* __restrict__ bias2)
{
    int wm = blockIdx.x >> 3, h = blockIdx.x & 7;
    __half* dst = bias2 + (size_t)blockIdx.x * 4096;
    for (int idx = threadIdx.x; idx < 4096; idx += 256) {
        int r = idx >> 6, c = idx & 63;
        float v = -30000.f;
        if (r < Nv && c < Nv) {
            int r1 = r / WSv, c1 = r % WSv;
            int r2 = c / WSv, c2 = c % WSv;
            int bi = (r1 - r2 + WSv - 1) * (2 * WSv - 1) + (c1 - c2 + WSv - 1);
            v = rel_bias[bi * NHv + h] + mask[wm * (Nv * Nv) + r * Nv + c];
        }
        dst[idx] = __float2half(v);
    }
}

// ---------------------------------------------------------------------------
// per-token LN stats (+ optional fp16 gathered copy)
// ---------------------------------------------------------------------------
__global__ __launch_bounds__(256) void ln_stats_kernel(
    const float* __restrict__ x, float* __restrict__ MU, float* __restrict__ RS,
    __half* __restrict__ XH, int mode)
{
    int warp = threadIdx.x >> 5, lane = threadIdx.x & 31;
    int t = blockIdx.x * 8 + warp;
    int src = mode ? win_src(t) : t;
    const float4* xr = (const float4*)(x + (size_t)src * Cv);
    float4 v0 = xr[lane], v1 = xr[lane + 32];
    float s  = v0.x + v0.y + v0.z + v0.w + v1.x + v1.y + v1.z + v1.w;
    float s2 = v0.x*v0.x + v0.y*v0.y + v0.z*v0.z + v0.w*v0.w
             + v1.x*v1.x + v1.y*v1.y + v1.z*v1.z + v1.w*v1.w;
    #pragma unroll
    for (int o = 16; o > 0; o >>= 1) {
        s  += __shfl_xor_sync(0xffffffffu, s,  o);
        s2 += __shfl_xor_sync(0xffffffffu, s2, o);
    }
    if (XH) {
        __half2* hr = (__half2*)(XH + (size_t)t * Cv);
        hr[lane * 2]      = __floats2half2_rn(v0.x, v0.y);
        hr[lane * 2 + 1]  = __floats2half2_rn(v0.z, v0.w);
        hr[64 + lane * 2]     = __floats2half2_rn(v1.x, v1.y);
        hr[64 + lane * 2 + 1] = __floats2half2_rn(v1.z, v1.w);
    }
    if (lane == 0) {
        float mu  = s * (1.f / Cv);
        float var = s2 * (1.f / Cv) - mu * mu;
        MU[t] = mu;
        RS[t] = rsqrtf(var + 1e-5f);
    }
}

// ---------------------------------------------------------------------------
// mma / ldmatrix helpers
// ---------------------------------------------------------------------------
__device__ __forceinline__ uint32_t smem_u32(const void* p) {
    uint32_t r;
    asm("{.reg .u64 t; cvta.to.shared.u64 t, %1; cvt.u32.u64 %0, t;}"
        : "=r"(r) : "l"(p));
    return r;
}
__device__ __forceinline__ void ldm_x4(uint32_t* r, uint32_t addr) {
    asm volatile("ldmatrix.sync.aligned.m8n8.x4.shared.b16 {%0,%1,%2,%3}, [%4];"
        : "=r"(r[0]), "=r"(r[1]), "=r"(r[2]), "=r"(r[3]) : "r"(addr));
}
__device__ __forceinline__ void ldm_x4_t(uint32_t* r, uint32_t addr) {
    asm volatile("ldmatrix.sync.aligned.m8n8.x4.trans.shared.b16 {%0,%1,%2,%3}, [%4];"
        : "=r"(r[0]), "=r"(r[1]), "=r"(r[2]), "=r"(r[3]) : "r"(addr));
}
__device__ __forceinline__ void mma_f16(float* c, const uint32_t* a, const uint32_t* b) {
    asm volatile(
        "mma.sync.aligned.m16n8k16.row.col.f32.f16.f16.f32 "
        "{%0,%1,%2,%3}, {%4,%5,%6,%7}, {%8,%9}, {%0,%1,%2,%3};"
        : "+f"(c[0]), "+f"(c[1]), "+f"(c[2]), "+f"(c[3])
        : "r"(a[0]), "r"(a[1]), "r"(a[2]), "r"(a[3]), "r"(b[0]), "r"(b[1]));
}
__device__ __forceinline__ uint32_t h2u(float a, float b) {
    __half2 h = __floats2half2_rn(a, b);
    return *(uint32_t*)&h;
}

// ---------------------------------------------------------------------------
// FP16 HMMA GEMM (R8, unchanged)
// ---------------------------------------------------------------------------
template<int LNEPI, int OMODE>
__global__ __launch_bounds__(256) void hgemm(
    const __half* __restrict__ A, const __half* __restrict__ Wh,
    const float* __restrict__ bias, const float* __restrict__ colsum,
    const float* __restrict__ MU, const float* __restrict__ RS,
    const float* __restrict__ res, void* __restrict__ Out,
    void* __restrict__ Out2, int M, int Nc, int K)
{
    extern __shared__ __half smh[];
    __half* As = smh;
    __half* Bs = smh + STG * STAGE_H;

    int tid  = threadIdx.x;
    int warp = tid >> 5, lane = tid & 31;
    int wm   = (warp >> 2) * 64;
    int wn   = (warp & 3) * 32;
    int bm   = blockIdx.y * 128, bn = blockIdx.x * 128;

    int lr = tid >> 1;
    int hc = (tid & 1) * 16;
    const __half* ga = A  + (size_t)(bm + lr) * K + hc;
    const __half* gb = Wh + (size_t)(bn + lr) * K + hc;
    uint32_t sAbase = smem_u32(As);
    uint32_t sBbase = smem_u32(Bs);
    uint32_t sA = sAbase + (uint32_t)(lr * SROWH + hc) * 2u;
    uint32_t sB = sBbase + (uint32_t)(lr * SROWH + hc) * 2u;
    const uint32_t stgB = STAGE_H * 2u;

    float acc[4][4][4];
    #pragma unroll
    for (int mt = 0; mt < 4; mt++)
        #pragma unroll
        for (int nt = 0; nt < 4; nt++)
            #pragma unroll
            for (int i = 0; i < 4; i++) acc[mt][nt][i] = 0.f;

    const int KT = K / 32;

    auto issue = [&](int j) {
        uint32_t da = sA + (uint32_t)(j % STG) * stgB;
        uint32_t db = sB + (uint32_t)(j % STG) * stgB;
        const __half* a0 = ga + (size_t)j * 32;
        const __half* b0 = gb + (size_t)j * 32;
        asm volatile(
            "cp.async.ca.shared.global [%0], [%1], 16;\n"
            "cp.async.ca.shared.global [%2], [%3], 16;\n"
            "cp.async.ca.shared.global [%4], [%5], 16;\n"
            "cp.async.ca.shared.global [%6], [%7], 16;\n"
            :: "r"(da), "l"(a0), "r"(da + 16), "l"(a0 + 8),
               "r"(db), "l"(b0), "r"(db + 16), "l"(b0 + 8)
            : "memory");
        asm volatile("cp.async.commit_group;" ::: "memory");
    };

    #pragma unroll
    for (int j = 0; j < STG - 1; j++) issue(j);

    int rla = lane & 15;
    int cla = (lane & 16) >> 1;
    int rlb = (lane & 7) | ((lane & 16) >> 1);
    int clb = lane & 8;

    for (int it = 0; it < KT; it++) {
        asm volatile("cp.async.wait_group %0;" :: "n"(STG - 2) : "memory");
        __syncthreads();

        if (it + STG - 1 < KT) issue(it + STG - 1);
        else asm volatile("cp.async.commit_group;" ::: "memory");

        uint32_t baseA = sAbase + (uint32_t)(it % STG) * stgB;
        uint32_t baseB = sBbase + (uint32_t)(it % STG) * stgB;

        #pragma unroll
        for (int ks = 0; ks < 2; ks++) {
            int kb = ks * 16;
            uint32_t a[4][4], bq[2][4];
            #pragma unroll
            for (int mt = 0; mt < 4; mt++)
                ldm_x4(a[mt], baseA + (uint32_t)((wm + mt * 16 + rla) * SROWH + kb + cla) * 2u);
            #pragma unroll
            for (int p = 0; p < 2; p++)
                ldm_x4(bq[p], baseB + (uint32_t)((wn + p * 16 + rlb) * SROWH + kb + clb) * 2u);
            #pragma unroll
            for (int mt = 0; mt < 4; mt++)
                #pragma unroll
                for (int nt = 0; nt < 4; nt++)
                    mma_f16(acc[mt][nt], a[mt], &bq[nt >> 1][(nt & 1) * 2]);
        }
    }
    asm volatile("cp.async.wait_all;" ::: "memory");

    const float INV_SQRT2 = 0.70710678118654752f;
    int qr = lane >> 2, qc = lane & 3;
    #pragma unroll
    for (int mt = 0; mt < 4; mt++) {
        #pragma unroll
        for (int half = 0; half < 2; half++) {
            int row = bm + wm + mt * 16 + qr + half * 8;
            float mu = 0.f, rs = 1.f;
            if (LNEPI) { mu = MU[row]; rs = RS[row]; }
            int orow = (OMODE == 2) ? inv_tok(row) : row;
            #pragma unroll
            for (int nt = 0; nt < 4; nt++) {
                int col = bn + wn + nt * 8 + qc * 2;
                float v0 = acc[mt][nt][half * 2 + 0];
                float v1 = acc[mt][nt][half * 2 + 1];
                if (LNEPI) {
                    float mrs = mu * rs;
                    v0 = v0 * rs - mrs * colsum[col]     + bias[col];
                    v1 = v1 * rs - mrs * colsum[col + 1] + bias[col + 1];
                } else {
                    v0 += bias[col];
                    v1 += bias[col + 1];
                }
                size_t oidx = (size_t)orow * Nc + col;
                if (OMODE == 0) {
                    *(__half2*)((__half*)Out + oidx) = __floats2half2_rn(v0, v1);
                } else if (OMODE == 1) {
                    v0 = 0.5f * v0 * (1.f + erff(v0 * INV_SQRT2));
                    v1 = 0.5f * v1 * (1.f + erff(v1 * INV_SQRT2));
                    *(__half2*)((__half*)Out + oidx) = __floats2half2_rn(v0, v1);
                } else if (OMODE == 2) {
                    v0 += res[oidx];
                    v1 += res[oidx + 1];
                    *(float2*)((float*)Out + oidx) = make_float2(v0, v1);
                    *(__half2*)((__half*)Out2 + oidx) = __floats2half2_rn(v0, v1);
                } else {
                    v0 += res[oidx];
                    v1 += res[oidx + 1];
                    *(float2*)((float*)Out + oidx) = make_float2(v0, v1);
                }
            }
        }
    }
}

// ---------------------------------------------------------------------------
// Tensor-core window attention. One block per (window, head), 4 warps;
// warp w owns rows [16w, 16w+16). Q/K/V staged 64x40 halves (zero-padded).
// Softmax in C-fragment registers; P repacked into A fragments directly.
// ---------------------------------------------------------------------------
__global__ __launch_bounds__(128) void attn_mma_kernel(
    const __half* __restrict__ qkv, const __half* __restrict__ bias2,
    __half* __restrict__ out)
{
    __shared__ __half qs[64 * SROWH];
    __shared__ __half ks[64 * SROWH];
    __shared__ __half vs[64 * SROWH];

    int blk  = blockIdx.x;
    int win  = blk >> 3;
    int head = blk & 7;
    int tid  = threadIdx.x;
    int warp = tid >> 5, lane = tid & 31;
    int base = win * Nv;

    // stage Q/K/V for this head: rows 0..48 real, 49..63 zero
    for (int i = tid; i < 3 * 64 * 4; i += 128) {
        int m  = i >> 8;          // 0=q 1=k 2=v
        int rc = i & 255;
        int row = rc >> 2, ch = rc & 3;
        uint4 val = make_uint4(0, 0, 0, 0);
        if (row < Nv)
            val = *(const uint4*)(qkv + (size_t)(base + row) * (3 * Cv)
                                  + m * Cv + head * HDv + ch * 8);
        __half* dst = (m == 0) ? qs : (m == 1) ? ks : vs;
        *(uint4*)(dst + row * SROWH + ch * 8) = val;
    }
    __syncthreads();

    uint32_t qb = smem_u32(qs), kb = smem_u32(ks), vb = smem_u32(vs);
    int rla = lane & 15;
    int cla = (lane & 16) >> 1;
    int rlb = (lane & 7) | ((lane & 16) >> 1);
    int clb = lane & 8;
    int m0 = warp * 16;

    // S = Q K^T  (16 x 64 slab per warp)
    float st[8][4];
    #pragma unroll
    for (int nt = 0; nt < 8; nt++)
        #pragma unroll
        for (int i = 0; i < 4; i++) st[nt][i] = 0.f;

    #pragma unroll
    for (int kc = 0; kc < 2; kc++) {
        uint32_t a[4];
        ldm_x4(a, qb + (uint32_t)((m0 + rla) * SROWH + kc * 16 + cla) * 2u);
        #pragma unroll
        for (int p = 0; p < 4; p++) {
            uint32_t b[4];
            ldm_x4(b, kb + (uint32_t)((p * 16 + rlb) * SROWH + kc * 16 + clb) * 2u);
            mma_f16(st[2 * p],     a, b);
            mma_f16(st[2 * p + 1], a, b + 2);
        }
    }

    // bias + softmax in fragments
    int qr = lane >> 2, qc = lane & 3;
    int r0 = m0 + qr, r1 = r0 + 8;
    const __half* bz = bias2 + (size_t)((win & 63) * NHv + head) * 4096;

    float mx0 = -1e30f, mx1 = -1e30f;
    #pragma unroll
    for (int nt = 0; nt < 8; nt++) {
        int c = nt * 8 + qc * 2;
        float2 f0 = __half22float2(*(const __half2*)(bz + r0 * 64 + c));
        float2 f1 = __half22float2(*(const __half2*)(bz + r1 * 64 + c));
        st[nt][0] += f0.x; st[nt][1] += f0.y;
        st[nt][2] += f1.x; st[nt][3] += f1.y;
        mx0 = fmaxf(mx0, fmaxf(st[nt][0], st[nt][1]));
        mx1 = fmaxf(mx1, fmaxf(st[nt][2], st[nt][3]));
    }
    mx0 = fmaxf(mx0, __shfl_xor_sync(0xffffffffu, mx0, 1));
    mx0 = fmaxf(mx0, __shfl_xor_sync(0xffffffffu, mx0, 2));
    mx1 = fmaxf(mx1, __shfl_xor_sync(0xffffffffu, mx1, 1));
    mx1 = fmaxf(mx1, __shfl_xor_sync(0xffffffffu, mx1, 2));

    float sm0 = 0.f, sm1 = 0.f;
    #pragma unroll
    for (int nt = 0; nt < 8; nt++) {
        st[nt][0] = __expf(st[nt][0] - mx0);
        st[nt][1] = __expf(st[nt][1] - mx0);
        st[nt][2] = __expf(st[nt][2] - mx1);
        st[nt][3] = __expf(st[nt][3] - mx1);
        sm0 += st[nt][0] + st[nt][1];
        sm1 += st[nt][2] + st[nt][3];
    }
    sm0 += __shfl_xor_sync(0xffffffffu, sm0, 1);
    sm0 += __shfl_xor_sync(0xffffffffu, sm0, 2);
    sm1 += __shfl_xor_sync(0xffffffffu, sm1, 1);
    sm1 += __shfl_xor_sync(0xffffffffu, sm1, 2);
    float inv0 = 1.f / sm0, inv1 = 1.f / sm1;
    #pragma unroll
    for (int nt = 0; nt < 8; nt++) {
        st[nt][0] *= inv0; st[nt][1] *= inv0;
        st[nt][2] *= inv1; st[nt][3] *= inv1;
    }

    // O = P V   (P from fragments; V via ldmatrix.trans)
    float of[4][4];
    #pragma unroll
    for (int nt = 0; nt < 4; nt++)
        #pragma unroll
        for (int i = 0; i < 4; i++) of[nt][i] = 0.f;

    #pragma unroll
    for (int kt = 0; kt < 4; kt++) {
        uint32_t pa[4];
        pa[0] = h2u(st[2 * kt][0],     st[2 * kt][1]);
        pa[1] = h2u(st[2 * kt][2],     st[2 * kt][3]);
        pa[2] = h2u(st[2 * kt + 1][0], st[2 * kt + 1][1]);
        pa[3] = h2u(st[2 * kt + 1][2], st[2 * kt + 1][3]);
        #pragma unroll
        for (int nb = 0; nb < 2; nb++) {
            uint32_t b[4];
            ldm_x4_t(b, vb + (uint32_t)((kt * 16 + rla) * SROWH + nb * 16 + cla) * 2u);
            mma_f16(of[nb * 2],     pa, b);
            mma_f16(of[nb * 2 + 1], pa, b + 2);
        }
    }

    // store (rows < 49 only)
    #pragma unroll
    for (int nt = 0; nt < 4; nt++) {
        int c = head * HDv + nt * 8 + qc * 2;
        if (r0 < Nv)
            *(__half2*)(out + (size_t)(base + r0) * Cv + c) = __floats2half2_rn(of[nt][0], of[nt][1]);
        if (r1 < Nv)
            *(__half2*)(out + (size_t)(base + r1) * Cv + c) = __floats2half2_rn(of[nt][2], of[nt][3]);
    }
}

// ---------------------------------------------------------------------------
extern "C" void kernel_launch(void* const* d_in, const int* in_sizes, int n_in,
                              void* d_out, int out_size)
{
    const float* x       = (const float*)d_in[0];
    const float* mask    = (const float*)d_in[1];
    const float* norm1_g = (const float*)d_in[2];
    const float* norm1_b = (const float*)d_in[3];
    const float* qkv_w   = (const float*)d_in[4];
    const float* qkv_b   = (const float*)d_in[5];
    const float* rel_bias= (const float*)d_in[6];
    const float* proj_w  = (const float*)d_in[7];
    const float* proj_b  = (const float*)d_in[8];
    const float* norm2_g = (const float*)d_in[9];
    const float* norm2_b = (const float*)d_in[10];
    const float* fc1_w   = (const float*)d_in[11];
    const float* fc1_b   = (const float*)d_in[12];
    const float* fc2_w   = (const float*)d_in[13];
    const float* fc2_b   = (const float*)d_in[14];
    float* out = (float*)d_out;

    __half *p_xh, *p_qkvh, *p_attoh, *p_x1h, *p_hidh, *p_bias2;
    __half *p_qkvwh, *p_fc1wh, *p_projwh, *p_fc2wh;
    float *p_x1, *p_mu1, *p_rs1, *p_mu2, *p_rs2;
    float *p_qkvbf, *p_qkvcs, *p_fc1bf, *p_fc1cs;
    cudaGetSymbolAddress((void**)&p_xh,     g_xh);
    cudaGetSymbolAddress((void**)&p_qkvh,   g_qkvh);
    cudaGetSymbolAddress((void**)&p_attoh,  g_attoh);
    cudaGetSymbolAddress((void**)&p_x1,     g_x1);
    cudaGetSymbolAddress((void**)&p_x1h,    g_x1h);
    cudaGetSymbolAddress((void**)&p_hidh,   g_hidh);
    cudaGetSymbolAddress((void**)&p_bias2,  g_bias2);
    cudaGetSymbolAddress((void**)&p_mu1,    g_mu1);
    cudaGetSymbolAddress((void**)&p_rs1,    g_rs1);
    cudaGetSymbolAddress((void**)&p_mu2,    g_mu2);
    cudaGetSymbolAddress((void**)&p_rs2,    g_rs2);
    cudaGetSymbolAddress((void**)&p_qkvwh,  g_qkvwh);
    cudaGetSymbolAddress((void**)&p_fc1wh,  g_fc1wh);
    cudaGetSymbolAddress((void**)&p_projwh, g_projwh);
    cudaGetSymbolAddress((void**)&p_fc2wh,  g_fc2wh);
    cudaGetSymbolAddress((void**)&p_qkvbf,  g_qkvbf);
    cudaGetSymbolAddress((void**)&p_qkvcs,  g_qkvcs);
    cudaGetSymbolAddress((void**)&p_fc1bf,  g_fc1bf);
    cudaGetSymbolAddress((void**)&p_fc1cs,  g_fc1cs);

    const int SMEM = STG * 2 * STAGE_H * 2;   // 61440 B
    static int attr_done = 0;
    if (!attr_done) {
        cudaFuncSetAttribute(hgemm<1,0>, cudaFuncAttributeMaxDynamicSharedMemorySize, SMEM);
        cudaFuncSetAttribute(hgemm<0,2>, cudaFuncAttributeMaxDynamicSharedMemorySize, SMEM);
        cudaFuncSetAttribute(hgemm<1,1>, cudaFuncAttributeMaxDynamicSharedMemorySize, SMEM);
        cudaFuncSetAttribute(hgemm<0,3>, cudaFuncAttributeMaxDynamicSharedMemorySize, SMEM);
        attr_done = 1;
    }

    // 0. weight prep (+ attention softmax scale folded into Q rows)
    fold_h_kernel<<<3 * Cv, 256>>>(qkv_w, qkv_b, norm1_g, norm1_b, p_qkvwh, p_qkvbf, p_qkvcs, Cv);
    fold_h_kernel<<<4 * Cv, 256>>>(fc1_w, fc1_b, norm2_g, norm2_b, p_fc1wh, p_fc1bf, p_fc1cs, 0);
    w2h_kernel<<<(Cv * Cv + 255) / 256, 256>>>(proj_w, p_projwh, Cv * Cv);
    w2h_kernel<<<(Cv * 4 * Cv + 255) / 256, 256>>>(fc2_w, p_fc2wh, Cv * 4 * Cv);
    bias2_kernel<<<NWIN * NHv, 256>>>(rel_bias, mask, p_bias2);

    // 1. LN1 stats + fp16 gathered x
    ln_stats_kernel<<<TOK / 8, 256>>>(x, p_mu1, p_rs1, p_xh, 1);

    // 2. QKV GEMM (LN epilogue, Q pre-scaled)
    {
        dim3 grid(3 * Cv / 128, TOK / 128);
        hgemm<1,0><<<grid, 256, SMEM>>>(p_xh, p_qkvwh, p_qkvbf, p_qkvcs,
                                        p_mu1, p_rs1, nullptr, p_qkvh, nullptr,
                                        TOK, 3 * Cv, Cv);
    }

    // 3. tensor-core window attention
    attn_mma_kernel<<<BW * NHv, 128>>>(p_qkvh, p_bias2, p_attoh);

    // 4. proj GEMM + window-reverse/unshift + residual(x) -> x1 fp32 + fp16
    {
        dim3 grid(Cv / 128, TOK / 128);
        hgemm<0,2><<<grid, 256, SMEM>>>(p_attoh, p_projwh, proj_b, nullptr,
                                        nullptr, nullptr, x, p_x1, p_x1h,
                                        TOK, Cv, Cv);
    }

    // 5. LN2 stats
    ln_stats_kernel<<<TOK / 8, 256>>>(p_x1, p_mu2, p_rs2, nullptr, 0);

    // 6. fc1 GEMM (LN2 epilogue) + GELU -> hid fp16
    {
        dim3 grid(4 * Cv / 128, TOK / 128);
        hgemm<1,1><<<grid, 256, SMEM>>>(p_x1h, p_fc1wh, p_fc1bf, p_fc1cs,
                                        p_mu2, p_rs2, nullptr, p_hidh, nullptr,
                                        TOK, 4 * Cv, Cv);
    }

    // 7. fc2 GEMM + residual(x1) -> out fp32
    {
        dim3 grid(Cv / 128, TOK / 128);
        hgemm<0,3><<<grid, 256, SMEM>>>(p_hidh, p_fc2wh, fc2_b, nullptr,
                                        nullptr, nullptr, p_x1, out, nullptr,
                                        TOK, Cv, 4 * Cv);
    }
}